// round 1
// baseline (speedup 1.0000x reference)
#include <cuda_runtime.h>

// HOG layer, fused single kernel.
// x: (64,1,512,512) f32. out: (64, 9*64*64) f32.
// Per block: one (image n, cell-row cy) stripe of 8 rows x 512 cols.
// 256 threads: thread t -> cell = t/4 (8 columns), sub = t%4 (2 rows).

#define TS 515  // smem tile row stride (odd-ish: 515 % 32 == 3 -> only 2-way LDS conflicts)

__device__ __forceinline__ void hog_accum(float gx, float gy, float* __restrict__ h)
{
    float d2  = fmaf(gx, gx, gy * gy);
    float mag = d2 * rsqrtf(fmaxf(d2, 1e-30f));     // == sqrtf(d2), 0-safe
    float ph  = atan2f(gx, gy);                     // ref: arctan2(gx, gy)
    float p   = ph * 2.8647889756541161f;           // * 9/pi, p in [-9, 9]

    int fl = __float2int_rd(p) + 9;                 // exact floor, [0, 18]
    int ce = __float2int_ru(p) + 9;                 // exact ceil,  [0, 18]
    if (fl >= 9) fl -= 9;
    if (fl >= 9) fl -= 9;
    if (ce >= 9) ce -= 9;
    if (ce >= 9) ce -= 9;

    h[fl << 8] += mag;                              // per-thread slot: bank == lane, conflict-free
    h[ce << 8] += mag;
}

__global__ __launch_bounds__(256)
void hog_kernel(const float* __restrict__ x, float* __restrict__ out)
{
    __shared__ float tile[10 * TS];
    __shared__ float hist[9 * 256];

    const int tid = threadIdx.x;
    const int bid = blockIdx.x;
    const int n   = bid >> 6;
    const int cy  = bid & 63;

    // zero per-thread histogram slots
#pragma unroll
    for (int b = 0; b < 9; ++b) hist[b * 256 + tid] = 0.0f;

    // ---- load 10 rows x 512 cols into smem (zero halo), float4 ----
    const float* img  = x + (size_t)n * (512 * 512);
    const int    row0 = cy * 8 - 1;
#pragma unroll
    for (int i = 0; i < 5; ++i) {
        int idx = tid + i * 256;          // 0..1279
        int r   = idx >> 7;               // 0..9
        int c4  = idx & 127;              // 0..127 float4 within row
        int gr  = row0 + r;
        float4 v = make_float4(0.f, 0.f, 0.f, 0.f);
        if ((unsigned)gr < 512u)
            v = *reinterpret_cast<const float4*>(img + (size_t)gr * 512 + c4 * 4);
        float* d = &tile[r * TS + 1 + c4 * 4];
        d[0] = v.x; d[1] = v.y; d[2] = v.z; d[3] = v.w;
    }
    if (tid < 10) { tile[tid * TS] = 0.f; tile[tid * TS + 513] = 0.f; }
    __syncthreads();

    // ---- compute: thread handles rows (2*sub, 2*sub+1) of cell (tid/4) ----
    const int cell = tid >> 2;
    const int sub  = tid & 3;
    const float* p0 = &tile[(2 * sub + 0) * TS + cell * 8];  // window cols 0..9
    const float* p1 = &tile[(2 * sub + 1) * TS + cell * 8];
    const float* p2 = &tile[(2 * sub + 2) * TS + cell * 8];
    const float* p3 = &tile[(2 * sub + 3) * TS + cell * 8];
    float* h = &hist[tid];

    float w0 = p0[0], w1 = p0[1];
    float a0 = p1[0], a1 = p1[1];
    float b0 = p2[0], b1 = p2[1];
    float c0 = p3[0], c1 = p3[1];
    // vertical [1,2,1] column sums for gx (row0 uses w,a,b; row1 uses a,b,c)
    float A0 = w0 + 2.f * a0 + b0;
    float A1 = w1 + 2.f * a1 + b1;
    float B0 = a0 + 2.f * b0 + c0;
    float B1 = a1 + 2.f * b1 + c1;

#pragma unroll
    for (int j = 2; j <= 9; ++j) {
        float w2 = p0[j], a2 = p1[j], b2 = p2[j], c2 = p3[j];
        float A2 = w2 + 2.f * a2 + b2;
        float B2 = a2 + 2.f * b2 + c2;

        // pixel (row 2*sub, col j-1): gx = colsum(left)-colsum(right); gy = toprow-botrow
        float gx0 = A0 - A2;
        float gy0 = (w0 + 2.f * w1 + w2) - (b0 + 2.f * b1 + b2);
        hog_accum(gx0, gy0, h);

        // pixel (row 2*sub+1, col j-1)
        float gx1 = B0 - B2;
        float gy1 = (a0 + 2.f * a1 + a2) - (c0 + 2.f * c1 + c2);
        hog_accum(gx1, gy1, h);

        w0 = w1; w1 = w2;  a0 = a1; a1 = a2;
        b0 = b1; b1 = b2;  c0 = c1; c1 = c2;
        A0 = A1; A1 = A2;  B0 = B1; B1 = B2;
    }
    __syncthreads();

    // ---- reduce 4 sub-threads per cell, mean over 8x8 = /64, write out ----
    if (sub == 0) {
        float* o = out + (size_t)n * 36864 + cy * 64 + cell;
#pragma unroll
        for (int b = 0; b < 9; ++b) {
            const float* hb = &hist[b * 256 + tid];   // tid == cell*4 here
            float s = hb[0] + hb[1] + hb[2] + hb[3];
            o[(size_t)b * 4096] = s * 0.015625f;      // 1/64
        }
    }
}

extern "C" void kernel_launch(void* const* d_in, const int* in_sizes, int n_in,
                              void* d_out, int out_size)
{
    const float* x = (const float*)d_in[0];
    float* out = (float*)d_out;
    (void)in_sizes; (void)n_in; (void)out_size;
    hog_kernel<<<4096, 256>>>(x, out);
}

// round 2
// speedup vs baseline: 1.1610x; 1.1610x over previous
#include <cuda_runtime.h>

// HOG layer, fused single kernel — no atan2, exact sector classification.
// x: (64,1,512,512) f32. out: (64, 9*64*64) f32.
// Block = one (image n, cell-row cy) stripe of 8 rows x 512 cols, 256 threads.
// thread t: cell = t/4 (8 cols), sub = t%4 (2 rows).

#define TS 515  // smem tile row stride (515 % 32 == 3 -> at worst 2-way LDS conflicts)

__device__ __forceinline__ void hog_accum(float gx, float gy, float* __restrict__ h)
{
    // magnitude
    float d2 = fmaf(gx, gx, gy * gy);
    float mag;
    asm("sqrt.approx.f32 %0, %1;" : "=f"(mag) : "f"(d2));   // sqrt.approx(0)=0, no guard needed

    // sector classification: p = atan2(gx,gy)*9/pi; need fl = floor(p), ce = fl+1.
    // Octant: sign(gx), sign(gy), swap = |gx|>|gy|. Within octant, compare
    // mn >= tan(theta_k)*mx  (exact boundary tests, no division).
    float aa = fabsf(gx), bb = fabsf(gy);
    bool  sw = aa > bb;
    float mxv = fmaxf(aa, bb);
    float mnv = fminf(aa, bb);
    float k1 = sw ? 0.17632698f : 0.36397023f;   // tan10 : tan20
    float k2 = sw ? 0.57735027f : 0.83909963f;   // tan30 : tan40
    int fa = (int)(mnv >= k1 * mxv) + (int)(mnv >= k2 * mxv);
    if (sw) fa = 4 - fa;                          // fa = floor(alpha*9/pi), alpha in [0,pi/2]
    bool ix = gx >= 0.0f;
    bool iy = gy >= 0.0f;
    int fl9 = ix ? 9 : 0;                         // slot index = floor(p)+9 in [0,17]
    fl9 = (ix != iy) ? (fl9 + 8 - fa) : (fl9 + fa);

    // two smem RMW updates: slots fl9, fl9+1 (second offset folds into LDS/STS imm)
    float* s = h + (fl9 << 8);
    s[0]   += mag;
    s[256] += mag;
}

__global__ __launch_bounds__(256)
void hog_kernel(const float* __restrict__ x, float* __restrict__ out)
{
    __shared__ float tile[10 * TS];
    __shared__ float hist[19 * 256];

    const int tid = threadIdx.x;
    const int bid = blockIdx.x;
    const int n   = bid >> 6;
    const int cy  = bid & 63;

    // zero per-thread histogram slots (19 raw slots, folded mod-9 at the end)
#pragma unroll
    for (int b = 0; b < 19; ++b) hist[b * 256 + tid] = 0.0f;

    // ---- load 10 rows x 512 cols into smem (zero halo), float4 ----
    const float* img  = x + (size_t)n * (512 * 512);
    const int    row0 = cy * 8 - 1;
#pragma unroll
    for (int i = 0; i < 5; ++i) {
        int idx = tid + i * 256;          // 0..1279
        int r   = idx >> 7;               // 0..9
        int c4  = idx & 127;              // float4 index within row
        int gr  = row0 + r;
        float4 v = make_float4(0.f, 0.f, 0.f, 0.f);
        if ((unsigned)gr < 512u)
            v = *reinterpret_cast<const float4*>(img + (size_t)gr * 512 + c4 * 4);
        float* d = &tile[r * TS + 1 + c4 * 4];
        d[0] = v.x; d[1] = v.y; d[2] = v.z; d[3] = v.w;
    }
    if (tid < 10) { tile[tid * TS] = 0.f; tile[tid * TS + 513] = 0.f; }
    __syncthreads();

    // ---- compute: thread handles rows (2*sub, 2*sub+1) of cell (tid/4) ----
    const int cell = tid >> 2;
    const int sub  = tid & 3;
    const float* p0 = &tile[(2 * sub + 0) * TS + cell * 8];
    const float* p1 = &tile[(2 * sub + 1) * TS + cell * 8];
    const float* p2 = &tile[(2 * sub + 2) * TS + cell * 8];
    const float* p3 = &tile[(2 * sub + 3) * TS + cell * 8];
    float* h = &hist[tid];

    float w0 = p0[0], w1 = p0[1];
    float a0 = p1[0], a1 = p1[1];
    float b0 = p2[0], b1 = p2[1];
    float c0 = p3[0], c1 = p3[1];
    float A0 = w0 + 2.f * a0 + b0;     // vertical [1,2,1] column sums
    float A1 = w1 + 2.f * a1 + b1;
    float B0 = a0 + 2.f * b0 + c0;
    float B1 = a1 + 2.f * b1 + c1;

#pragma unroll
    for (int j = 2; j <= 9; ++j) {
        float w2 = p0[j], a2 = p1[j], b2 = p2[j], c2 = p3[j];
        float A2 = w2 + 2.f * a2 + b2;
        float B2 = a2 + 2.f * b2 + c2;

        float gx0 = A0 - A2;
        float gy0 = (w0 + 2.f * w1 + w2) - (b0 + 2.f * b1 + b2);
        hog_accum(gx0, gy0, h);

        float gx1 = B0 - B2;
        float gy1 = (a0 + 2.f * a1 + a2) - (c0 + 2.f * c1 + c2);
        hog_accum(gx1, gy1, h);

        w0 = w1; w1 = w2;  a0 = a1; a1 = a2;
        b0 = b1; b1 = b2;  c0 = c1; c1 = c2;
        A0 = A1; A1 = A2;  B0 = B1; B1 = B2;
    }
    __syncthreads();

    // ---- fold 19 raw slots -> 9 bins, reduce 4 sub-threads, mean /64, write ----
    if (sub == 0) {
        float* o = out + (size_t)n * 36864 + cy * 64 + cell;
        const float* hb = &hist[tid];     // tid == cell*4 here
        float e18 = hb[18 * 256] + hb[18 * 256 + 1] + hb[18 * 256 + 2] + hb[18 * 256 + 3];
#pragma unroll
        for (int b = 0; b < 9; ++b) {
            const float* lo = &hb[b * 256];
            const float* hi = &hb[(b + 9) * 256];
            float s = lo[0] + lo[1] + lo[2] + lo[3]
                    + hi[0] + hi[1] + hi[2] + hi[3];
            if (b == 0) s += e18;
            o[(size_t)b * 4096] = s * 0.015625f;   // 1/64
        }
    }
}

extern "C" void kernel_launch(void* const* d_in, const int* in_sizes, int n_in,
                              void* d_out, int out_size)
{
    const float* x = (const float*)d_in[0];
    float* out = (float*)d_out;
    (void)in_sizes; (void)n_in; (void)out_size;
    hog_kernel<<<4096, 256>>>(x, out);
}

// round 3
// speedup vs baseline: 1.3983x; 1.2043x over previous
#include <cuda_runtime.h>

// HOG layer fused kernel, R3: conflict-free padded tile + single-RMW prefix histogram.
// x: (64,1,512,512) f32. out: (64, 9*64*64) f32.
// Block = one (image n, cell-row cy) stripe of 8 rows x 512 cols, 256 threads.
// thread t: cell = t/4 (8 cols), sub = t%4 (2 rows).
//
// Tile layout: column c stored at index c + c/8 + 2 (pad slot between cells)
//  -> 8 same-sub lanes read at 9-float stride: banks {0,9,18,27,4,13,22,31}, conflict-free.
// Histogram: P[fl9] += mag once per pixel; fold raw[s]=P[s]+P[s-1] at the end
//  (exactly equivalent to adding mag to slots fl9 and fl9+1).

#define TS 579   // padded tile row stride in floats (512 data + 64 pads + 2 halo + 1)

__device__ __forceinline__ void hog_accum(float gx, float gy, float* __restrict__ h)
{
    float d2 = fmaf(gx, gx, gy * gy);
    float mag;
    asm("sqrt.approx.f32 %0, %1;" : "=f"(mag) : "f"(d2));   // sqrt.approx(0)=0

    // fl = floor(atan2(gx,gy)*9/pi); exact boundary tests, no division/atan.
    float aa = fabsf(gx), bb = fabsf(gy);
    bool  sw = aa > bb;
    float mxv = fmaxf(aa, bb);
    float mnv = fminf(aa, bb);
    float k1 = sw ? 0.17632698f : 0.36397023f;   // tan10 : tan20
    float k2 = sw ? 0.57735027f : 0.83909963f;   // tan30 : tan40
    int fa = (int)(mnv >= k1 * mxv) + (int)(mnv >= k2 * mxv);
    if (sw) fa = 4 - fa;                          // floor(alpha*9/pi), alpha in [0,pi/2]
    bool ix = gx >= 0.0f;
    bool iy = gy >= 0.0f;
    int fl9 = ix ? 9 : 0;                         // slot = floor(p)+9 in [0,17]
    fl9 = (ix != iy) ? (fl9 + 8 - fa) : (fl9 + fa);

    h[fl9 << 8] += mag;                           // ONE smem RMW per pixel
}

__global__ __launch_bounds__(256)
void hog_kernel(const float* __restrict__ x, float* __restrict__ out)
{
    __shared__ float tile[10 * TS];
    __shared__ float hist[18 * 256];

    const int tid = threadIdx.x;
    const int bid = blockIdx.x;
    const int n   = bid >> 6;
    const int cy  = bid & 63;

    // zero per-thread P slots
#pragma unroll
    for (int b = 0; b < 18; ++b) hist[b * 256 + tid] = 0.0f;

    // ---- load 10 rows x 512 cols into padded tile (zero halo) ----
    const float* img  = x + (size_t)n * (512 * 512);
    const int    row0 = cy * 8 - 1;
#pragma unroll
    for (int i = 0; i < 5; ++i) {
        int idx = tid + i * 256;          // 0..1279
        int r   = idx >> 7;               // 0..9
        int k   = idx & 127;              // float4 index within row
        int gr  = row0 + r;
        float4 v = make_float4(0.f, 0.f, 0.f, 0.f);
        if ((unsigned)gr < 512u)
            v = *reinterpret_cast<const float4*>(img + (size_t)gr * 512 + k * 4);
        // col 4k -> tile index 4k + (4k)/8 + 2 = 4k + (k>>1) + 2 ; 4 cols same cell
        float* d = &tile[r * TS + 4 * k + (k >> 1) + 2];
        d[0] = v.x; d[1] = v.y; d[2] = v.z; d[3] = v.w;
    }
    if (tid < 10) { tile[tid * TS] = 0.f; tile[tid * TS + 578] = 0.f; }  // col -1, col 512
    __syncthreads();

    // ---- compute: thread handles rows (2*sub, 2*sub+1) of cell (tid/4) ----
    const int cell = tid >> 2;
    const int sub  = tid & 3;
    const float* p0 = &tile[(2 * sub + 0) * TS + 9 * cell];
    const float* p1 = &tile[(2 * sub + 1) * TS + 9 * cell];
    const float* p2 = &tile[(2 * sub + 2) * TS + 9 * cell];
    const float* p3 = &tile[(2 * sub + 3) * TS + 9 * cell];
    float* h = &hist[tid];

    // window column offsets within padded tile (cols 8c-1 .. 8c+8)
    const int OFF[10] = {0, 2, 3, 4, 5, 6, 7, 8, 9, 11};

    float w0 = p0[OFF[0]], w1 = p0[OFF[1]];
    float a0 = p1[OFF[0]], a1 = p1[OFF[1]];
    float b0 = p2[OFF[0]], b1 = p2[OFF[1]];
    float c0 = p3[OFF[0]], c1 = p3[OFF[1]];
    float A0 = w0 + 2.f * a0 + b0;     // vertical [1,2,1] column sums
    float A1 = w1 + 2.f * a1 + b1;
    float B0 = a0 + 2.f * b0 + c0;
    float B1 = a1 + 2.f * b1 + c1;

#pragma unroll
    for (int j = 2; j <= 9; ++j) {
        int o = OFF[j];
        float w2 = p0[o], a2 = p1[o], b2 = p2[o], c2 = p3[o];
        float A2 = w2 + 2.f * a2 + b2;
        float B2 = a2 + 2.f * b2 + c2;

        float gx0 = A0 - A2;
        float gy0 = (w0 + 2.f * w1 + w2) - (b0 + 2.f * b1 + b2);
        hog_accum(gx0, gy0, h);

        float gx1 = B0 - B2;
        float gy1 = (a0 + 2.f * a1 + a2) - (c0 + 2.f * c1 + c2);
        hog_accum(gx1, gy1, h);

        w0 = w1; w1 = w2;  a0 = a1; a1 = a2;
        b0 = b1; b1 = b2;  c0 = c1; c1 = c2;
        A0 = A1; A1 = A2;  B0 = B1; B1 = B2;
    }
    __syncthreads();

    // ---- fold: raw[s] = P[s]+P[s-1]; bin[b] = raw[b]+raw[b+9] (+raw[18] for b=0) ----
    // per-thread: bins from own 18 P slots (conflict-free: bank == lane)
    {
        float P[18];
#pragma unroll
        for (int s = 0; s < 18; ++s) P[s] = h[s << 8];
        float bin[9];
        bin[0] = P[0] + P[8] + P[9] + P[17];
#pragma unroll
        for (int b = 1; b < 9; ++b) bin[b] = P[b - 1] + P[b] + P[b + 8] + P[b + 9];
        __syncthreads();
#pragma unroll
        for (int b = 0; b < 9; ++b) h[b << 8] = bin[b];
    }
    __syncthreads();

    // ---- reduce 4 sub-threads per cell, mean /64, write ----
    if (sub == 0) {
        float* o = out + (size_t)n * 36864 + cy * 64 + cell;
        const float* hb = &hist[tid];     // tid == cell*4
#pragma unroll
        for (int b = 0; b < 9; ++b) {
            const float* q = &hb[b * 256];
            float s = q[0] + q[1] + q[2] + q[3];
            o[(size_t)b * 4096] = s * 0.015625f;   // 1/64
        }
    }
}

extern "C" void kernel_launch(void* const* d_in, const int* in_sizes, int n_in,
                              void* d_out, int out_size)
{
    const float* x = (const float*)d_in[0];
    float* out = (float*)d_out;
    (void)in_sizes; (void)n_in; (void)out_size;
    hog_kernel<<<4096, 256>>>(x, out);
}

// round 4
// speedup vs baseline: 1.4179x; 1.0140x over previous
#include <cuda_runtime.h>
#include <cstdint>

// HOG layer fused kernel, R4: overlapped paired histogram RMW (inline PTX),
// register fold + shuffle reduce epilogue, single __syncthreads.
// x: (64,1,512,512) f32. out: (64, 9*64*64) f32.
// Block = one (image n, cell-row cy) stripe of 8 rows x 512 cols, 256 threads.
// thread t: cell = t/4 (8 cols), sub = t%4 (2 rows).

#define TS 579   // padded tile row stride (col c at index c + c/8 + 2; 9-float cell stride)

__device__ __forceinline__ uint32_t smem_u32(const void* p)
{
    uint32_t a;
    asm("{ .reg .u64 t; cvta.to.shared.u64 t, %1; cvt.u32.u64 %0, t; }"
        : "=r"(a) : "l"(p));
    return a;
}

// slot byte-offset (fl9 * 256 floats * 4B) + magnitude for one pixel
__device__ __forceinline__ uint32_t hog_class(float gx, float gy, float& mag)
{
    float d2 = fmaf(gx, gx, gy * gy);
    asm("sqrt.approx.f32 %0, %1;" : "=f"(mag) : "f"(d2));   // sqrt.approx(0)=0

    // fl9 = floor(atan2(gx,gy)*9/pi)+9 in [0,17]; exact tan-boundary tests.
    float aa = fabsf(gx), bb = fabsf(gy);
    bool  sw = aa > bb;
    float mxv = fmaxf(aa, bb);
    float mnv = fminf(aa, bb);
    float k1 = sw ? 0.17632698f : 0.36397023f;   // tan10 : tan20
    float k2 = sw ? 0.57735027f : 0.83909963f;   // tan30 : tan40
    int fa = (int)(mnv >= k1 * mxv) + (int)(mnv >= k2 * mxv);
    if (sw) fa = 4 - fa;
    bool ix = gx >= 0.0f;
    bool iy = gy >= 0.0f;
    int fl9 = ix ? 9 : 0;
    fl9 = (ix != iy) ? (fl9 + 8 - fa) : (fl9 + fa);
    return (uint32_t)fl9 << 10;
}

// Two histogram updates with overlapped smem chains.
// If slots equal: one RMW with m0+m1. Else: two provably-disjoint RMWs,
// hand-ordered so both LDS issue before either STS (latencies overlap).
__device__ __forceinline__ void hog_pair(uint32_t hb,
                                         float gx0, float gy0,
                                         float gx1, float gy1)
{
    float m0, m1;
    uint32_t a0 = hb + hog_class(gx0, gy0, m0);
    uint32_t a1 = hb + hog_class(gx1, gy1, m1);
    float msum = m0 + m1;
    asm volatile(
        "{\n\t"
        ".reg .pred p;\n\t"
        ".reg .f32 t0, t1, v0;\n\t"
        "setp.ne.u32 p, %0, %1;\n\t"
        "selp.f32 v0, %2, %3, p;\n\t"
        "ld.shared.f32 t0, [%0];\n\t"
        "@p ld.shared.f32 t1, [%1];\n\t"
        "add.f32 t0, t0, v0;\n\t"
        "@p add.f32 t1, t1, %4;\n\t"
        "st.shared.f32 [%0], t0;\n\t"
        "@p st.shared.f32 [%1], t1;\n\t"
        "}"
        :: "r"(a0), "r"(a1), "f"(m0), "f"(msum), "f"(m1) : "memory");
}

__global__ __launch_bounds__(256)
void hog_kernel(const float* __restrict__ x, float* __restrict__ out)
{
    __shared__ float tile[10 * TS];
    __shared__ float hist[18 * 256];

    const int tid = threadIdx.x;
    const int bid = blockIdx.x;
    const int n   = bid >> 6;
    const int cy  = bid & 63;

    // zero own P column (thread-private: no sync needed)
#pragma unroll
    for (int b = 0; b < 18; ++b) hist[b * 256 + tid] = 0.0f;

    // ---- load 10 rows x 512 cols into padded tile (zero halo) ----
    const float* img  = x + (size_t)n * (512 * 512);
    const int    row0 = cy * 8 - 1;
#pragma unroll
    for (int i = 0; i < 5; ++i) {
        int idx = tid + i * 256;          // 0..1279
        int r   = idx >> 7;               // 0..9
        int k   = idx & 127;              // float4 index within row
        int gr  = row0 + r;
        float4 v = make_float4(0.f, 0.f, 0.f, 0.f);
        if ((unsigned)gr < 512u)
            v = *reinterpret_cast<const float4*>(img + (size_t)gr * 512 + k * 4);
        float* d = &tile[r * TS + 4 * k + (k >> 1) + 2];
        d[0] = v.x; d[1] = v.y; d[2] = v.z; d[3] = v.w;
    }
    if (tid < 10) { tile[tid * TS] = 0.f; tile[tid * TS + 578] = 0.f; }  // col -1, col 512
    __syncthreads();

    // ---- compute: thread handles rows (2*sub, 2*sub+1) of cell (tid/4) ----
    const int cell = tid >> 2;
    const int sub  = tid & 3;
    const float* p0 = &tile[(2 * sub + 0) * TS + 9 * cell];
    const float* p1 = &tile[(2 * sub + 1) * TS + 9 * cell];
    const float* p2 = &tile[(2 * sub + 2) * TS + 9 * cell];
    const float* p3 = &tile[(2 * sub + 3) * TS + 9 * cell];
    const uint32_t hb = smem_u32(&hist[tid]);

    const int OFF[10] = {0, 2, 3, 4, 5, 6, 7, 8, 9, 11};

    float w0 = p0[OFF[0]], w1 = p0[OFF[1]];
    float a0 = p1[OFF[0]], a1 = p1[OFF[1]];
    float b0 = p2[OFF[0]], b1 = p2[OFF[1]];
    float c0 = p3[OFF[0]], c1 = p3[OFF[1]];
    float A0 = w0 + 2.f * a0 + b0;     // vertical [1,2,1] column sums
    float A1 = w1 + 2.f * a1 + b1;
    float B0 = a0 + 2.f * b0 + c0;
    float B1 = a1 + 2.f * b1 + c1;

#pragma unroll
    for (int j = 2; j <= 9; ++j) {
        int o = OFF[j];
        float w2 = p0[o], a2 = p1[o], b2 = p2[o], c2 = p3[o];
        float A2 = w2 + 2.f * a2 + b2;
        float B2 = a2 + 2.f * b2 + c2;

        float gx0 = A0 - A2;
        float gy0 = (w0 + 2.f * w1 + w2) - (b0 + 2.f * b1 + b2);
        float gx1 = B0 - B2;
        float gy1 = (a0 + 2.f * a1 + a2) - (c0 + 2.f * c1 + c2);
        hog_pair(hb, gx0, gy0, gx1, gy1);

        w0 = w1; w1 = w2;  a0 = a1; a1 = a2;
        b0 = b1; b1 = b2;  c0 = c1; c1 = c2;
        A0 = A1; A1 = A2;  B0 = B1; B1 = B2;
    }

    // ---- fold own P column -> 9 bins (registers), shuffle-reduce 4 subs, write ----
    // raw[s] = P[s] + P[s-1]; bin[b] = raw[b] + raw[b+9] (+ raw[18] into bin 0)
    float P[18];
#pragma unroll
    for (int s = 0; s < 18; ++s) P[s] = hist[s * 256 + tid];
    float bin[9];
    bin[0] = (P[0] + P[8]) + (P[9] + P[17]);
#pragma unroll
    for (int b = 1; b < 9; ++b) bin[b] = (P[b - 1] + P[b]) + (P[b + 8] + P[b + 9]);

#pragma unroll
    for (int b = 0; b < 9; ++b) {
        bin[b] += __shfl_xor_sync(0xffffffffu, bin[b], 1);
        bin[b] += __shfl_xor_sync(0xffffffffu, bin[b], 2);
    }

    if (sub == 0) {
        float* o = out + (size_t)n * 36864 + cy * 64 + cell;
#pragma unroll
        for (int b = 0; b < 9; ++b)
            o[(size_t)b * 4096] = bin[b] * 0.015625f;   // 1/64
    }
}

extern "C" void kernel_launch(void* const* d_in, const int* in_sizes, int n_in,
                              void* d_out, int out_size)
{
    const float* x = (const float*)d_in[0];
    float* out = (float*)d_out;
    (void)in_sizes; (void)n_in; (void)out_size;
    hog_kernel<<<4096, 256>>>(x, out);
}

// round 5
// speedup vs baseline: 1.4642x; 1.0326x over previous
#include <cuda_runtime.h>
#include <cstdint>

// HOG fused kernel R5: float2 tile (cell stride 10), float-pipe sector classify
// with float->int magic addressing, single-RMW prefix histogram.
// x: (64,1,512,512) f32. out: (64, 9*64*64) f32.
// Block = (image n, cell-row cy) stripe, 256 threads: cell = t/4, sub = t%4 (2 rows).
// Tile layout: col c -> 10*(c>>3) + (c&7) + 4 ; idx1 = left edge halo, idx644 = right.

#define TS2 646   // even row stride; 646%32=6 -> cross-row banks verified conflict-free

__device__ __forceinline__ uint32_t smem_u32(const void* p)
{
    uint32_t a;
    asm("{ .reg .u64 t; cvta.to.shared.u64 t, %1; cvt.u32.u64 %0, t; }"
        : "=r"(a) : "l"(p));
    return a;
}

__device__ __forceinline__ float setge(float a, float b)
{
    float r;
    asm("set.ge.f32.f32 %0, %1, %2;" : "=f"(r) : "f"(a), "f"(b));
    return r;  // 1.0f or 0.0f, fma-pipe FSET
}

// returns smem byte address of slot fl9 (= floor(atan2(gx,gy)*9/pi)+9) in this
// thread's histogram column; mag by reference.
__device__ __forceinline__ uint32_t hog_class(float gx, float gy, uint32_t hb, float& mag)
{
    float d2 = fmaf(gx, gx, gy * gy);
    asm("sqrt.approx.f32 %0, %1;" : "=f"(mag) : "f"(d2));

    float u = fabsf(gx), v = fabsf(gy);
    float fa = (setge(u, 0.36397023f * v) + setge(u, 0.83909963f * v))
             + (setge(u, 1.73205081f * v) + setge(u, 5.67128182f * v));  // 0..4

    uint32_t bx = __float_as_uint(gx), by = __float_as_uint(gy);
    uint32_t xo = bx ^ by;
    // negate fa iff signs differ (pure sign-bit xor)
    float negfa = __uint_as_float(__float_as_uint(fa) ^ (xo & 0x80000000u));
    // base const: (gx>=0,same)->9, (gx>=0,diff)->17, (gx<0,diff)->8, (gx<0,same)->0
    float cf = ((int)bx < 0) ? (((int)xo < 0) ? 8.0f : 0.0f)
                             : (((int)xo < 0) ? 17.0f : 9.0f);
    float m = (cf + negfa) + 12582912.0f;        // 0x4B400000 + fl9 (exact)
    return hb + (__float_as_uint(m) << 10);      // 0x4B400000<<10 == 0 mod 2^32
}

// two hist RMWs with overlapped LDS; merged when same slot.
__device__ __forceinline__ void hog_pair(uint32_t a0, float m0, uint32_t a1, float m1)
{
    float msum = m0 + m1;
    asm volatile(
        "{\n\t"
        ".reg .pred p;\n\t"
        ".reg .f32 t0, t1, v0;\n\t"
        "setp.ne.u32 p, %0, %1;\n\t"
        "selp.f32 v0, %2, %3, p;\n\t"
        "ld.shared.f32 t0, [%0];\n\t"
        "@p ld.shared.f32 t1, [%1];\n\t"
        "add.f32 t0, t0, v0;\n\t"
        "@p add.f32 t1, t1, %4;\n\t"
        "st.shared.f32 [%0], t0;\n\t"
        "@p st.shared.f32 [%1], t1;\n\t"
        "}"
        :: "r"(a0), "r"(a1), "f"(m0), "f"(msum), "f"(m1));
}

__device__ __forceinline__ void emit(uint32_t hb, float gx0, float gy0, float gx1, float gy1)
{
    float m0, m1;
    uint32_t q0 = hog_class(gx0, gy0, hb, m0);
    uint32_t q1 = hog_class(gx1, gy1, hb, m1);
    hog_pair(q0, m0, q1, m1);
}

__global__ __launch_bounds__(256)
void hog_kernel(const float* __restrict__ x, float* __restrict__ out)
{
    __shared__ __align__(16) float tile[10 * TS2];
    __shared__ float hist[18 * 256];

    const int tid = threadIdx.x;
    const int n   = blockIdx.x >> 6;
    const int cy  = blockIdx.x & 63;

#pragma unroll
    for (int b = 0; b < 18; ++b) hist[b * 256 + tid] = 0.0f;

    // ---- load 10 rows into padded tile ----
    const float* img  = x + (size_t)n * (512 * 512);
    const int    row0 = cy * 8 - 1;
#pragma unroll
    for (int i = 0; i < 5; ++i) {
        int idx = tid + i * 256;          // 0..1279
        int r   = idx >> 7;
        int k   = idx & 127;              // float4 index in row
        int gr  = row0 + r;
        float4 v = make_float4(0.f, 0.f, 0.f, 0.f);
        if ((unsigned)gr < 512u)
            v = *reinterpret_cast<const float4*>(img + (size_t)gr * 512 + k * 4);
        float* d = &tile[r * TS2 + 5 * k + 4 - (k & 1)];   // always even index
        *reinterpret_cast<float2*>(d)     = make_float2(v.x, v.y);
        *reinterpret_cast<float2*>(d + 2) = make_float2(v.z, v.w);
    }
    if (tid < 10) { tile[tid * TS2 + 1] = 0.f; tile[tid * TS2 + 644] = 0.f; }
    __syncthreads();

    // ---- mainloop: thread = cell (8 cols) x 2 rows; 2 cols per step ----
    const int cell = tid >> 2;
    const int sub  = tid & 3;
    const float* pw = &tile[(2 * sub + 0) * TS2 + 10 * cell];
    const float* pa = &tile[(2 * sub + 1) * TS2 + 10 * cell];
    const float* pb = &tile[(2 * sub + 2) * TS2 + 10 * cell];
    const float* pc = &tile[(2 * sub + 3) * TS2 + 10 * cell];
    const uint32_t hb = smem_u32(&hist[tid]);

    // left halo (col -1) + first pair (cols 0,1)
    float lw = pw[1], la = pa[1], lb = pb[1], lc = pc[1];
    float2 wp = *reinterpret_cast<const float2*>(pw + 4);
    float2 ap = *reinterpret_cast<const float2*>(pa + 4);
    float2 bp = *reinterpret_cast<const float2*>(pb + 4);
    float2 cp = *reinterpret_cast<const float2*>(pc + 4);

    float Am1 = lw + 2.f * la + lb;                 // S[-1] top
    float Bm1 = la + 2.f * lb + lc;                 // S[-1] bottom
    float A0 = wp.x + 2.f * ap.x + bp.x, A1 = wp.y + 2.f * ap.y + bp.y;
    float B0 = ap.x + 2.f * bp.x + cp.x, B1 = ap.y + 2.f * bp.y + cp.y;

    // emit col 0
    emit(hb,
         Am1 - A1, (lw + 2.f * wp.x + wp.y) - (lb + 2.f * bp.x + bp.y),
         Bm1 - B1, (la + 2.f * ap.x + ap.y) - (lc + 2.f * cp.x + cp.y));

    float w0 = wp.x, w1 = wp.y, a0 = ap.x, a1 = ap.y;
    float b0 = bp.x, b1 = bp.y, c0 = cp.x, c1 = cp.y;

#pragma unroll
    for (int k = 1; k < 4; ++k) {
        float2 wn = *reinterpret_cast<const float2*>(pw + 4 + 2 * k);
        float2 an = *reinterpret_cast<const float2*>(pa + 4 + 2 * k);
        float2 bn = *reinterpret_cast<const float2*>(pb + 4 + 2 * k);
        float2 cn = *reinterpret_cast<const float2*>(pc + 4 + 2 * k);
        float A2 = wn.x + 2.f * an.x + bn.x, A3 = wn.y + 2.f * an.y + bn.y;
        float B2 = an.x + 2.f * bn.x + cn.x, B3 = an.y + 2.f * bn.y + cn.y;

        // emit col 2k-1
        emit(hb,
             A0 - A2, (w0 + 2.f * w1 + wn.x) - (b0 + 2.f * b1 + bn.x),
             B0 - B2, (a0 + 2.f * a1 + an.x) - (c0 + 2.f * c1 + cn.x));
        // emit col 2k
        emit(hb,
             A1 - A3, (w1 + 2.f * wn.x + wn.y) - (b1 + 2.f * bn.x + bn.y),
             B1 - B3, (a1 + 2.f * an.x + an.y) - (c1 + 2.f * cn.x + cn.y));

        w0 = wn.x; w1 = wn.y; a0 = an.x; a1 = an.y;
        b0 = bn.x; b1 = bn.y; c0 = cn.x; c1 = cn.y;
        A0 = A2; A1 = A3; B0 = B2; B1 = B3;
    }

    // right halo (col 8) + emit col 7
    {
        float rw = pw[14], ra = pa[14], rb = pb[14], rc = pc[14];
        float A8 = rw + 2.f * ra + rb;
        float B8 = ra + 2.f * rb + rc;
        emit(hb,
             A0 - A8, (w0 + 2.f * w1 + rw) - (b0 + 2.f * b1 + rb),
             B0 - B8, (a0 + 2.f * a1 + ra) - (c0 + 2.f * c1 + rc));
    }

    asm volatile("" ::: "memory");   // order fold reads after asm RMWs

    // ---- fold P -> 9 bins in registers, shuffle-reduce 4 subs, write ----
    float P[18];
#pragma unroll
    for (int s = 0; s < 18; ++s) P[s] = hist[s * 256 + tid];
    float bin[9];
    bin[0] = (P[0] + P[8]) + (P[9] + P[17]);
#pragma unroll
    for (int b = 1; b < 9; ++b) bin[b] = (P[b - 1] + P[b]) + (P[b + 8] + P[b + 9]);

#pragma unroll
    for (int b = 0; b < 9; ++b) {
        bin[b] += __shfl_xor_sync(0xffffffffu, bin[b], 1);
        bin[b] += __shfl_xor_sync(0xffffffffu, bin[b], 2);
    }

    if (sub == 0) {
        float* o = out + (size_t)n * 36864 + cy * 64 + cell;
#pragma unroll
        for (int b = 0; b < 9; ++b)
            o[(size_t)b * 4096] = bin[b] * 0.015625f;   // 1/64
    }
}

extern "C" void kernel_launch(void* const* d_in, const int* in_sizes, int n_in,
                              void* d_out, int out_size)
{
    const float* x = (const float*)d_in[0];
    float* out = (float*)d_out;
    (void)in_sizes; (void)n_in; (void)out_size;
    hog_kernel<<<4096, 256>>>(x, out);
}